// round 16
// baseline (speedup 1.0000x reference)
#include <cuda_runtime.h>
#include <cuda_fp16.h>
#include <mma.h>
#include <cstdint>

using namespace nvcuda;

#define BB 1024
#define CC 1000
#define HH 512
#define NEG_INF (__int_as_float(0xff800000))

// ---------------- scratch (__device__ globals; zero-initialized) ----------------
__device__ float g_GA[1024 * 1024];           // split-K Gram partial (K 0..255)
__device__ float g_GB[1024 * 1024];           // split-K Gram partial (K 256..511)
__device__ float g_normA[1024];               // diagonal partials (consistent norms)
__device__ float g_normB[1024];
__device__ float g_ymax[BB];
__device__ int   g_jmax[BB];

// ---------------------------------------------------------------------------
// k_main: bid < 272  -> fused convert+Gram 64x64 tile (tensor/L2-bound)
//         bid >= 272 -> one y-row: copy into out + argmax (DRAM-bound, hides
//                       under gram; also warms L2 with y for k_bot)
// ---------------------------------------------------------------------------
#define NTT 16
#define NPAIR (NTT * (NTT + 1) / 2)   // 136
#define NGRAM (2 * NPAIR)             // 272
#define KHALF (HH / 2)                // 256
#define SST2 264                      // fp16 smem stride: 33r%32 distinct
#define OPHALF (64 * SST2)
#define SMEMSZ (2 * OPHALF * 2)       // 67584 B dynamic smem

extern __shared__ char dsm[];

__global__ void __launch_bounds__(256, 2)
k_main(const float* __restrict__ w,
       const float* __restrict__ y,
       float* __restrict__ out) {
    const int t = threadIdx.x;
    const int lane = t & 31, wid = t >> 5;

    if (blockIdx.x >= NGRAM) {
        // ---------------- copy + argmax: one y-row per block ----------------
        float* sv = (float*)dsm;
        int*   si = (int*)(dsm + 64);
        const int b = blockIdx.x - NGRAM;
        float* orow = out + (long)b * (CC + 1);

        float vmax = NEG_INF; int imax = 0x7fffffff;
        if (t < CC / 4) {
            const float4 vy = __ldg((const float4*)(y + (long)b * CC) + t);
            const int c = t * 4;
            orow[c] = vy.x; orow[c + 1] = vy.y; orow[c + 2] = vy.z; orow[c + 3] = vy.w;
            vmax = vy.x; imax = c;
            if (vy.y > vmax) { vmax = vy.y; imax = c + 1; }
            if (vy.z > vmax) { vmax = vy.z; imax = c + 2; }
            if (vy.w > vmax) { vmax = vy.w; imax = c + 3; }
        }
        #pragma unroll
        for (int o = 16; o > 0; o >>= 1) {
            const float v2 = __shfl_xor_sync(0xffffffffu, vmax, o);
            const int   i2 = __shfl_xor_sync(0xffffffffu, imax, o);
            if (v2 > vmax || (v2 == vmax && i2 < imax)) { vmax = v2; imax = i2; }
        }
        if (lane == 0) { sv[wid] = vmax; si[wid] = imax; }
        __syncthreads();
        if (t == 0) {
            float bv = sv[0]; int bi = si[0];
            #pragma unroll
            for (int k = 1; k < 8; k++)
                if (sv[k] > bv || (sv[k] == bv && si[k] < bi)) { bv = sv[k]; bi = si[k]; }
            g_ymax[b] = bv; g_jmax[b] = bi;
        }
        return;
    }

    // ---------------- fused convert + Gram tile ----------------
    __half* sA = (__half*)dsm;
    __half* sB = sA + OPHALF;
    float* Cs = (float*)dsm;          // epilogue overlay: 64x68 f32

    const int wr = (wid >> 1) * 16;   // 0..48
    const int wc = (wid & 1) * 32;    // 0,32

    const int kh = blockIdx.x & 1;
    int p = blockIdx.x >> 1, ti = 0;
    while (p >= NTT - ti) { p -= NTT - ti; ti++; }
    const int tj = ti + p;
    const int k0 = kh * KHALF;

    // Phase 1: load f32 tiles, convert, store fp16 to smem (once, full K-half)
    #pragma unroll
    for (int i = 0; i < 16; i++) {
        const int idx = i * 256 + t;          // < 4096
        const int fr = idx >> 6;
        const int fc = (idx & 63) * 4;
        const int ra = min(ti * 64 + fr, CC - 1);
        const int rb = min(tj * 64 + fr, CC - 1);
        const float4 va = __ldg((const float4*)(w + (long)ra * HH + k0 + fc));
        const float4 vb = __ldg((const float4*)(w + (long)rb * HH + k0 + fc));
        uint32_t a0, a1, b0, b1;
        asm("cvt.rn.f16x2.f32 %0, %1, %2;" : "=r"(a0) : "f"(va.y), "f"(va.x));
        asm("cvt.rn.f16x2.f32 %0, %1, %2;" : "=r"(a1) : "f"(va.w), "f"(va.z));
        asm("cvt.rn.f16x2.f32 %0, %1, %2;" : "=r"(b0) : "f"(vb.y), "f"(vb.x));
        asm("cvt.rn.f16x2.f32 %0, %1, %2;" : "=r"(b1) : "f"(vb.w), "f"(vb.z));
        *(uint2*)&sA[fr * SST2 + fc] = make_uint2(a0, a1);
        *(uint2*)&sB[fr * SST2 + fc] = make_uint2(b0, b1);
    }
    __syncthreads();

    // Phase 2: MMA sweep, K=256 in 16 steps, no syncs
    wmma::fragment<wmma::accumulator, 16, 16, 16, float> acc[2];
    wmma::fill_fragment(acc[0], 0.f);
    wmma::fill_fragment(acc[1], 0.f);

    #pragma unroll
    for (int kk = 0; kk < KHALF; kk += 16) {
        wmma::fragment<wmma::matrix_a, 16, 16, 16, __half, wmma::row_major> af;
        wmma::fragment<wmma::matrix_b, 16, 16, 16, __half, wmma::col_major> bf[2];
        wmma::load_matrix_sync(af, sA + wr * SST2 + kk, SST2);
        wmma::load_matrix_sync(bf[0], sB + wc * SST2 + kk, SST2);
        wmma::load_matrix_sync(bf[1], sB + (wc + 16) * SST2 + kk, SST2);
        wmma::mma_sync(acc[0], af, bf[0], acc[0]);
        wmma::mma_sync(acc[1], af, bf[1], acc[1]);
    }

    // Epilogue: smem round-trip, coalesced upper + mirror stores
    __syncthreads();
    #pragma unroll
    for (int j = 0; j < 2; j++)
        wmma::store_matrix_sync(Cs + wr * 68 + wc + 16 * j, acc[j], 68,
                                wmma::mem_row_major);
    __syncthreads();

    float* G = kh ? g_GB : g_GA;
    for (int idx = t; idx < 64 * 16; idx += 256) {       // upper tile
        const int r = idx >> 4, c4 = idx & 15;
        const float4 v = *(const float4*)(Cs + r * 68 + c4 * 4);
        *(float4*)&G[(long)(ti * 64 + r) * 1024 + tj * 64 + c4 * 4] = v;
    }
    for (int idx = t; idx < 64 * 16; idx += 256) {       // mirror (transposed)
        const int c = idx >> 4, r4 = idx & 15;
        float4 v;
        v.x = Cs[(4 * r4 + 0) * 68 + c];
        v.y = Cs[(4 * r4 + 1) * 68 + c];
        v.z = Cs[(4 * r4 + 2) * 68 + c];
        v.w = Cs[(4 * r4 + 3) * 68 + c];
        *(float4*)&G[(long)(tj * 64 + c) * 1024 + ti * 64 + 4 * r4] = v;
    }
    if (ti == tj && t < 64)            // consistent norms from diagonal
        (kh ? g_normB : g_normA)[ti * 64 + t] = Cs[t * 68 + t];
}

// ---------------------------------------------------------------------------
// k_bot (lean): j/ymax known at entry -> y, G-rows and norms all load
// concurrently, no pre-memory barrier. 1024 blocks x 256 threads.
// ---------------------------------------------------------------------------
__global__ void __launch_bounds__(256)
k_bot(const float* __restrict__ y,
      const float* __restrict__ eps_p,
      const float* __restrict__ lip_p,
      float* __restrict__ out) {
    const int b = blockIdx.x;
    const int t = threadIdx.x;
    const int lane = t & 31, wid = t >> 5;
    __shared__ float sm[8];

    const int   j    = g_jmax[b];
    const float ymax = g_ymax[b];
    const float s  = (*eps_p) * fabsf(*lip_p);
    const float s2 = s * s;
    const float nj = g_normA[j] + g_normB[j];

    float best = NEG_INF;
    if (t < CC / 4) {
        const float4 vy = __ldg((const float4*)(y + (long)b * CC) + t);
        const float4 ga = *((const float4*)(g_GA + (long)j * 1024) + t);
        const float4 gb = *((const float4*)(g_GB + (long)j * 1024) + t);
        const float4 na = *((const float4*)g_normA + t);
        const float4 nb = *((const float4*)g_normB + t);
        const float ye[4] = {vy.x, vy.y, vy.z, vy.w};
        const float ge[4] = {ga.x + gb.x, ga.y + gb.y, ga.z + gb.z, ga.w + gb.w};
        const float ne[4] = {na.x + nb.x, na.y + nb.y, na.z + nb.z, na.w + nb.w};
        #pragma unroll
        for (int e = 0; e < 4; e++) {
            if (ye[e] == ymax) continue;        // ref masks y==ymax -> -inf
            float sq = fmaf(-2.f, ge[e], nj + ne[e]);
            if (sq < 0.f) sq = 0.f;
            const float d = best - ye[e];
            if (d <= 0.f || sq * s2 > d * d)
                best = fmaxf(best, fmaf(s, sqrtf(sq), ye[e]));
        }
    }
    #pragma unroll
    for (int o = 16; o > 0; o >>= 1)
        best = fmaxf(best, __shfl_xor_sync(0xffffffffu, best, o));
    if (lane == 0) sm[wid] = best;
    __syncthreads();
    if (t == 0) {
        float r = sm[0];
        #pragma unroll
        for (int k = 1; k < 8; k++) r = fmaxf(r, sm[k]);
        out[(long)b * (CC + 1) + CC] = r;
    }
}

// ---------------------------------------------------------------------------
extern "C" void kernel_launch(void* const* d_in, const int* in_sizes, int n_in,
                              void* d_out, int out_size) {
    const float* y   = (const float*)d_in[0];
    const float* w   = (const float*)d_in[1];
    const float* eps = (const float*)d_in[2];
    const float* lip = (const float*)d_in[3];
    float* out = (float*)d_out;

    static bool attr = false;
    if (!attr) {
        cudaFuncSetAttribute(k_main, cudaFuncAttributeMaxDynamicSharedMemorySize,
                             SMEMSZ);
        attr = true;
    }

    k_main<<<NGRAM + BB, 256, SMEMSZ>>>(w, y, out);
    k_bot<<<BB, 256>>>(y, eps, lip, out);
}